// round 1
// baseline (speedup 1.0000x reference)
#include <cuda_runtime.h>
#include <cuda_bf16.h>
#include <math.h>

// Problem constants
#define Bb   2
#define Tt   2048
#define Dd   2048
#define Hh   16
#define HDd  128
#define LATd 512
#define RDd  64
#define CDd  64
#define Mrows (Bb*Tt)   // 4096

// ---------------------------------------------------------------------------
// Scratch (static device globals; no allocation allowed)
// ---------------------------------------------------------------------------
__device__ float g_q [Mrows * (Hh*HDd)];   // (4096, 2048)  q proj (rope applied in-place)
__device__ float g_kv[Mrows * (2*LATd)];   // (4096, 1024)  [k_lat | v_lat]
__device__ float g_kr[Mrows * RDd];        // (4096, 64)    shared rope key (rope in-place)
__device__ float g_kc[Mrows * (Hh*CDd)];   // (4096, 1024)  k content up-proj
__device__ float g_v [Mrows * (Hh*HDd)];   // (4096, 2048)  v up-proj
__device__ float g_ao[Mrows * (Hh*HDd)];   // (4096, 2048)  attention output

// ---------------------------------------------------------------------------
// SGEMM: C(M,N) = A(M,K) @ W(N,K)^T + bias(N)
// A row-major with leading dim lda; W row-major (N,K); C row-major ldc.
// 128x128 tile, BK=8, 256 threads, 8x8 per thread.
// M and K must be multiples of 128 / 8 (true for all calls). N guarded.
// ---------------------------------------------------------------------------
__global__ void __launch_bounds__(256) sgemm_bias(
    const float* __restrict__ A, int lda,
    const float* __restrict__ W,
    const float* __restrict__ bias,
    float* __restrict__ C, int ldc,
    int M, int N, int K)
{
    __shared__ float As[8][128];
    __shared__ float Bs[8][128];

    const int tid = threadIdx.x;
    const int tr  = tid >> 4;          // 0..15 -> rows tr*8..+7
    const int tc  = tid & 15;          // 0..15 -> cols tc*8..+7
    const int bm  = blockIdx.y * 128;
    const int bn  = blockIdx.x * 128;

    const int lrow = tid >> 1;         // 0..127
    const int lk   = (tid & 1) * 4;    // 0 or 4

    float acc[8][8];
    #pragma unroll
    for (int i = 0; i < 8; i++)
        #pragma unroll
        for (int j = 0; j < 8; j++) acc[i][j] = 0.f;

    const float* Aptr = A + (size_t)(bm + lrow) * lda + lk;
    const float* Wptr = W + (size_t)(bn + lrow) * K   + lk;
    const bool   bvalid = (bn + lrow) < N;

    for (int k0 = 0; k0 < K; k0 += 8) {
        float4 av = *(const float4*)(Aptr + k0);
        float4 bv = bvalid ? *(const float4*)(Wptr + k0)
                           : make_float4(0.f, 0.f, 0.f, 0.f);
        As[lk+0][lrow] = av.x; As[lk+1][lrow] = av.y;
        As[lk+2][lrow] = av.z; As[lk+3][lrow] = av.w;
        Bs[lk+0][lrow] = bv.x; Bs[lk+1][lrow] = bv.y;
        Bs[lk+2][lrow] = bv.z; Bs[lk+3][lrow] = bv.w;
        __syncthreads();

        #pragma unroll
        for (int k = 0; k < 8; k++) {
            float ar[8], br[8];
            *(float4*)(ar)     = *(const float4*)&As[k][tr*8];
            *(float4*)(ar + 4) = *(const float4*)&As[k][tr*8 + 4];
            *(float4*)(br)     = *(const float4*)&Bs[k][tc*8];
            *(float4*)(br + 4) = *(const float4*)&Bs[k][tc*8 + 4];
            #pragma unroll
            for (int i = 0; i < 8; i++)
                #pragma unroll
                for (int j = 0; j < 8; j++)
                    acc[i][j] += ar[i] * br[j];
        }
        __syncthreads();
    }

    #pragma unroll
    for (int i = 0; i < 8; i++) {
        const int row = bm + tr*8 + i;
        #pragma unroll
        for (int j = 0; j < 8; j++) {
            const int col = bn + tc*8 + j;
            if (col < N)
                C[(size_t)row * ldc + col] = acc[i][j] + bias[col];
        }
    }
}

// ---------------------------------------------------------------------------
// RoPE (rotate-half). RD=64, half=32.
// ---------------------------------------------------------------------------
__device__ __forceinline__ void rope_pair(float* p, int i, int t)
{
    float inv_freq = powf(10000.f, -(float)i / 32.f);
    float ang = (float)t * inv_freq;
    float s, c;
    sincosf(ang, &s, &c);
    float x1 = p[i];
    float x2 = p[i + 32];
    p[i]      = x1 * c - x2 * s;
    p[i + 32] = x2 * c + x1 * s;
}

__global__ void rope_kr_kernel(float* __restrict__ kr)
{
    int row = blockIdx.x;              // b*T + t
    int t   = row & (Tt - 1);
    rope_pair(kr + (size_t)row * RDd, threadIdx.x, t);
}

__global__ void rope_q_kernel(float* __restrict__ qb)
{
    int row = blockIdx.x;              // b*T + t
    int h   = blockIdx.y;
    int t   = row & (Tt - 1);
    rope_pair(qb + (size_t)row * (Hh*HDd) + h*HDd + CDd, threadIdx.x, t);
}

// ---------------------------------------------------------------------------
// Flash-style causal attention, fp32.
// One block per (q-tile of 64, head, batch). 256 threads.
// Shared: Qs 64x128, Ks 64x128, Vs 64x128, Ps 64x64, stats.
// Thread t: query row r = t>>2 ; column group c0 = (t&3)*16 for scores;
//           dim chunk d0 = (t&3)*32 for the O accumulator.
// ---------------------------------------------------------------------------
#define ATT_SMEM_FLOATS (3*64*128 + 64*64 + 3*64)
#define ATT_SMEM_BYTES  (ATT_SMEM_FLOATS * 4)

__global__ void __launch_bounds__(256) attn_kernel(
    const float* __restrict__ q,   // (4096, 2048)
    const float* __restrict__ kc,  // (4096, 1024)
    const float* __restrict__ kr,  // (4096, 64)
    const float* __restrict__ v,   // (4096, 2048)
    float* __restrict__ o)         // (4096, 2048)
{
    extern __shared__ float sm[];
    float* Qs = sm;                 // 64*128
    float* Ks = Qs + 64*128;
    float* Vs = Ks + 64*128;
    float* Ps = Vs + 64*128;        // 64*64
    float* Ms = Ps + 64*64;         // 64 row max
    float* Ls = Ms + 64;            // 64 row sum
    float* Cs = Ls + 64;            // 64 correction factors

    const int qt  = blockIdx.x;     // 0..31
    const int h   = blockIdx.y;
    const int b   = blockIdx.z;
    const int tid = threadIdx.x;
    const int qbase = qt * 64;
    const size_t rowbase = (size_t)b * Tt;

    // Load Q tile (64 x 128), vectorized
    for (int i = tid; i < 64*32; i += 256) {
        int r  = i >> 5;
        int c4 = i & 31;
        *(float4*)(Qs + r*128 + c4*4) =
            *(const float4*)(q + (rowbase + qbase + r) * (Hh*HDd) + h*HDd + c4*4);
    }
    if (tid < 64) { Ms[tid] = -INFINITY; Ls[tid] = 0.f; }

    float acc[32];
    #pragma unroll
    for (int j = 0; j < 32; j++) acc[j] = 0.f;

    const int r  = tid >> 2;
    const int c0 = (tid & 3) * 16;
    const int d0 = (tid & 3) * 32;
    const float scale = 0.08838834764831845f;   // 1/sqrt(128)

    __syncthreads();

    for (int kb = 0; kb <= qt; kb++) {
        const int kbase = kb * 64;

        // Load K (content | rope) and V tiles
        for (int i = tid; i < 64*32; i += 256) {
            int rr = i >> 5;
            int c4 = i & 31;
            size_t trow = rowbase + kbase + rr;
            float4 kval;
            if (c4 < 16)
                kval = *(const float4*)(kc + trow * (Hh*CDd) + h*CDd + c4*4);
            else
                kval = *(const float4*)(kr + trow * RDd + (c4-16)*4);
            *(float4*)(Ks + rr*128 + c4*4) = kval;
            *(float4*)(Vs + rr*128 + c4*4) =
                *(const float4*)(v + trow * (Hh*HDd) + h*HDd + c4*4);
        }
        __syncthreads();

        // Scores: row r, cols c0..c0+15
        float s[16];
        #pragma unroll
        for (int j = 0; j < 16; j++) s[j] = 0.f;
        #pragma unroll 4
        for (int d = 0; d < 128; d += 4) {
            float4 q4 = *(const float4*)(Qs + r*128 + d);
            #pragma unroll
            for (int j = 0; j < 16; j++) {
                float4 k4 = *(const float4*)(Ks + (c0+j)*128 + d);
                s[j] += q4.x*k4.x + q4.y*k4.y + q4.z*k4.z + q4.w*k4.w;
            }
        }
        const bool diag = (kb == qt);
        #pragma unroll
        for (int j = 0; j < 16; j++) {
            float val = s[j] * scale;
            if (diag && (c0 + j) > r) val = -INFINITY;   // kbase==qbase on diag
            Ps[r*64 + c0 + j] = val;
        }
        __syncthreads();

        // Online softmax row stats (64 threads, one per row)
        if (tid < 64) {
            float* prow = Ps + tid*64;
            float m_old = Ms[tid];
            float mx = m_old;
            #pragma unroll
            for (int c = 0; c < 64; c++) mx = fmaxf(mx, prow[c]);
            float cf = __expf(m_old - mx);      // 0 when m_old == -inf
            float sum = 0.f;
            #pragma unroll
            for (int c = 0; c < 64; c++) {
                float p = __expf(prow[c] - mx); // exp(-inf) == 0 for masked
                prow[c] = p;
                sum += p;
            }
            Ls[tid] = Ls[tid] * cf + sum;
            Ms[tid] = mx;
            Cs[tid] = cf;
        }
        __syncthreads();

        // O update: row r, dims d0..d0+31
        const float cf = Cs[r];
        #pragma unroll
        for (int j = 0; j < 32; j++) acc[j] *= cf;
        for (int c = 0; c < 64; c++) {
            float p = Ps[r*64 + c];
            const float* vrow = Vs + c*128 + d0;
            #pragma unroll
            for (int j = 0; j < 32; j += 4) {
                float4 v4 = *(const float4*)(vrow + j);
                acc[j]   += p * v4.x;
                acc[j+1] += p * v4.y;
                acc[j+2] += p * v4.z;
                acc[j+3] += p * v4.w;
            }
        }
        __syncthreads();   // protect Ks/Vs/Ps before next tile load
    }

    const float inv_l = 1.f / Ls[r];
    float* orow = o + (rowbase + qbase + r) * (Hh*HDd) + h*HDd + d0;
    #pragma unroll
    for (int j = 0; j < 32; j += 4) {
        float4 v4 = make_float4(acc[j]*inv_l, acc[j+1]*inv_l,
                                acc[j+2]*inv_l, acc[j+3]*inv_l);
        *(float4*)(orow + j) = v4;
    }
}

// ---------------------------------------------------------------------------
// Launch
// ---------------------------------------------------------------------------
extern "C" void kernel_launch(void* const* d_in, const int* in_sizes, int n_in,
                              void* d_out, int out_size)
{
    const float* x   = (const float*)d_in[0];
    const float* Wq  = (const float*)d_in[1];
    const float* bq  = (const float*)d_in[2];
    const float* Wkv = (const float*)d_in[3];
    const float* bkv = (const float*)d_in[4];
    const float* Wkr = (const float*)d_in[5];
    const float* bkr = (const float*)d_in[6];
    const float* Wku = (const float*)d_in[7];
    const float* bku = (const float*)d_in[8];
    const float* Wvu = (const float*)d_in[9];
    const float* bvu = (const float*)d_in[10];
    const float* Wo  = (const float*)d_in[11];
    const float* bo  = (const float*)d_in[12];
    float* out = (float*)d_out;

    float *qb, *kvb, *krb, *kcb, *vb, *ob;
    cudaGetSymbolAddress((void**)&qb,  g_q);
    cudaGetSymbolAddress((void**)&kvb, g_kv);
    cudaGetSymbolAddress((void**)&krb, g_kr);
    cudaGetSymbolAddress((void**)&kcb, g_kc);
    cudaGetSymbolAddress((void**)&vb,  g_v);
    cudaGetSymbolAddress((void**)&ob,  g_ao);

    cudaFuncSetAttribute(attn_kernel,
                         cudaFuncAttributeMaxDynamicSharedMemorySize,
                         ATT_SMEM_BYTES);

    const dim3 blk(256);

    // Projections from x
    sgemm_bias<<<dim3(16, 32), blk>>>(x, Dd, Wq,  bq,  qb,  Hh*HDd, Mrows, Hh*HDd, Dd);
    sgemm_bias<<<dim3(8,  32), blk>>>(x, Dd, Wkv, bkv, kvb, 2*LATd, Mrows, 2*LATd, Dd);
    sgemm_bias<<<dim3(1,  32), blk>>>(x, Dd, Wkr, bkr, krb, RDd,    Mrows, RDd,    Dd);

    // RoPE on shared rope-key (broadcast-invariant: same as per-head rope)
    rope_kr_kernel<<<Mrows, 32>>>(krb);

    // Up-projections from latents
    sgemm_bias<<<dim3(8,  32), blk>>>(kvb,          2*LATd, Wku, bku, kcb, Hh*CDd, Mrows, Hh*CDd, LATd);
    sgemm_bias<<<dim3(16, 32), blk>>>(kvb + LATd,   2*LATd, Wvu, bvu, vb,  Hh*HDd, Mrows, Hh*HDd, LATd);

    // RoPE on q's trailing RD dims of each head
    rope_q_kernel<<<dim3(Mrows, Hh), 32>>>(qb);

    // Causal flash attention
    attn_kernel<<<dim3(Tt/64, Hh, Bb), blk, ATT_SMEM_BYTES>>>(qb, kcb, krb, vb, ob);

    // Output projection -> d_out
    sgemm_bias<<<dim3(16, 32), blk>>>(ob, Hh*HDd, Wo, bo, out, Dd, Mrows, Dd, Dd);
}

// round 3
// speedup vs baseline: 1.1389x; 1.1389x over previous
#include <cuda_runtime.h>
#include <cuda_bf16.h>
#include <math.h>
#include <stdint.h>

// Problem constants
#define Bb   2
#define Tt   2048
#define Dd   2048
#define Hh   16
#define HDd  128
#define LATd 512
#define RDd  64
#define CDd  64
#define Mrows (Bb*Tt)   // 4096

// ---------------------------------------------------------------------------
// Scratch (static device globals; no allocation allowed)
// ---------------------------------------------------------------------------
__device__ float g_q [Mrows * (Hh*HDd)];   // (4096, 2048)
__device__ float g_kv[Mrows * (2*LATd)];   // (4096, 1024)
__device__ float g_kr[Mrows * RDd];        // (4096, 64)
__device__ float g_kc[Mrows * (Hh*CDd)];   // (4096, 1024)
__device__ float g_v [Mrows * (Hh*HDd)];   // (4096, 2048)
__device__ float g_ao[Mrows * (Hh*HDd)];   // (4096, 2048)

// ---------------------------------------------------------------------------
// TF32 tensor-core GEMM: C(M,N) = A(M,K) @ W(N,K)^T + bias(N)
// A row-major lda; W row-major (N,K) == col-major B -> matches mma ".col" B.
// 128x128x32 tiles, 256 threads (8 warps), warp tile 64x32 (4x4 m16n8k8).
// M % 128 == 0, K % 32 == 0 (true for all calls). N guarded.
// ---------------------------------------------------------------------------
#define BM 128
#define BN 128
#define BK 32
#define LDS_PAD 4
#define LDAs (BK + LDS_PAD)   // 36: stride%32==4 -> conflict-free frag loads

__device__ __forceinline__ uint32_t f2tf32(float f) {
    uint32_t r;
    asm("cvt.rna.tf32.f32 %0, %1;" : "=r"(r) : "f"(f));
    return r;
}

__device__ __forceinline__ void mma_tf32(
    float& c0, float& c1, float& c2, float& c3,
    uint32_t a0, uint32_t a1, uint32_t a2, uint32_t a3,
    uint32_t b0, uint32_t b1)
{
    asm volatile(
        "mma.sync.aligned.m16n8k8.row.col.f32.tf32.tf32.f32 "
        "{%0,%1,%2,%3}, {%4,%5,%6,%7}, {%8,%9}, {%0,%1,%2,%3};\n"
        : "+f"(c0), "+f"(c1), "+f"(c2), "+f"(c3)
        : "r"(a0), "r"(a1), "r"(a2), "r"(a3), "r"(b0), "r"(b1));
}

__global__ void __launch_bounds__(256) gemm_tf32(
    const float* __restrict__ A, int lda,
    const float* __restrict__ W,
    const float* __restrict__ bias,
    float* __restrict__ C, int ldc,
    int M, int N, int K)
{
    __shared__ uint32_t As[BM][LDAs];
    __shared__ uint32_t Bs[BN][LDAs];

    const int tid  = threadIdx.x;
    const int warp = tid >> 5;
    const int lane = tid & 31;
    const int g    = lane >> 2;      // group id 0..7
    const int tg   = lane & 3;       // thread-in-group 0..3
    const int wm   = warp & 1;       // 2 warps along M
    const int wn   = warp >> 1;      // 4 warps along N
    const int bm   = blockIdx.y * BM;
    const int bn   = blockIdx.x * BN;
    const int wr0  = wm * 64;        // warp row offset in tile
    const int wn0  = wn * 32;        // warp col offset in tile

    float acc[4][4][4];
    #pragma unroll
    for (int mi = 0; mi < 4; mi++)
        #pragma unroll
        for (int ni = 0; ni < 4; ni++)
            #pragma unroll
            for (int r = 0; r < 4; r++) acc[mi][ni][r] = 0.f;

    for (int k0 = 0; k0 < K; k0 += BK) {
        // load 128x32 of A and W into smem, converting to tf32 bits
        #pragma unroll
        for (int it = 0; it < 4; it++) {
            int idx = tid + it * 256;        // 0..1023 float4 slots
            int row = idx >> 3;
            int k4  = (idx & 7) * 4;
            float4 av = *(const float4*)(A + (size_t)(bm + row) * lda + k0 + k4);
            As[row][k4+0] = f2tf32(av.x);
            As[row][k4+1] = f2tf32(av.y);
            As[row][k4+2] = f2tf32(av.z);
            As[row][k4+3] = f2tf32(av.w);
            int nrow = bn + row;
            float4 bv = (nrow < N) ? *(const float4*)(W + (size_t)nrow * K + k0 + k4)
                                   : make_float4(0.f, 0.f, 0.f, 0.f);
            Bs[row][k4+0] = f2tf32(bv.x);
            Bs[row][k4+1] = f2tf32(bv.y);
            Bs[row][k4+2] = f2tf32(bv.z);
            Bs[row][k4+3] = f2tf32(bv.w);
        }
        __syncthreads();

        #pragma unroll
        for (int kk = 0; kk < BK; kk += 8) {
            uint32_t af[4][4], bf[4][2];
            #pragma unroll
            for (int mi = 0; mi < 4; mi++) {
                int r0 = wr0 + mi * 16 + g;
                af[mi][0] = As[r0    ][kk + tg];
                af[mi][1] = As[r0 + 8][kk + tg];
                af[mi][2] = As[r0    ][kk + tg + 4];
                af[mi][3] = As[r0 + 8][kk + tg + 4];
            }
            #pragma unroll
            for (int ni = 0; ni < 4; ni++) {
                int n0 = wn0 + ni * 8 + g;
                bf[ni][0] = Bs[n0][kk + tg];
                bf[ni][1] = Bs[n0][kk + tg + 4];
            }
            #pragma unroll
            for (int mi = 0; mi < 4; mi++)
                #pragma unroll
                for (int ni = 0; ni < 4; ni++)
                    mma_tf32(acc[mi][ni][0], acc[mi][ni][1],
                             acc[mi][ni][2], acc[mi][ni][3],
                             af[mi][0], af[mi][1], af[mi][2], af[mi][3],
                             bf[ni][0], bf[ni][1]);
        }
        __syncthreads();
    }

    // epilogue: D[row][col] layout of m16n8 atom
    #pragma unroll
    for (int mi = 0; mi < 4; mi++) {
        int row0 = bm + wr0 + mi * 16 + g;
        #pragma unroll
        for (int ni = 0; ni < 4; ni++) {
            int col = bn + wn0 + ni * 8 + 2 * tg;
            if (col < N) {
                float b0 = bias[col];
                float b1 = bias[col + 1];   // col+1 < N (N even, atoms aligned)
                float* p0 = C + (size_t)row0 * ldc + col;
                float* p1 = C + (size_t)(row0 + 8) * ldc + col;
                p0[0] = acc[mi][ni][0] + b0;
                p0[1] = acc[mi][ni][1] + b1;
                p1[0] = acc[mi][ni][2] + b0;
                p1[1] = acc[mi][ni][3] + b1;
            }
        }
    }
}

// ---------------------------------------------------------------------------
// RoPE (rotate-half). RD=64, half=32.
// ---------------------------------------------------------------------------
__device__ __forceinline__ void rope_pair(float* p, int i, int t)
{
    float inv_freq = powf(10000.f, -(float)i / 32.f);
    float ang = (float)t * inv_freq;
    float s, c;
    sincosf(ang, &s, &c);
    float x1 = p[i];
    float x2 = p[i + 32];
    p[i]      = x1 * c - x2 * s;
    p[i + 32] = x2 * c + x1 * s;
}

__global__ void rope_kr_kernel(float* __restrict__ kr)
{
    int row = blockIdx.x;
    int t   = row & (Tt - 1);
    rope_pair(kr + (size_t)row * RDd, threadIdx.x, t);
}

__global__ void rope_q_kernel(float* __restrict__ qb)
{
    int row = blockIdx.x;
    int h   = blockIdx.y;
    int t   = row & (Tt - 1);
    rope_pair(qb + (size_t)row * (Hh*HDd) + h*HDd + CDd, threadIdx.x, t);
}

// ---------------------------------------------------------------------------
// Flash-style causal attention, fp32 (unchanged this round).
// ---------------------------------------------------------------------------
#define ATT_SMEM_FLOATS (3*64*128 + 64*64 + 3*64)
#define ATT_SMEM_BYTES  (ATT_SMEM_FLOATS * 4)

__global__ void __launch_bounds__(256) attn_kernel(
    const float* __restrict__ q,
    const float* __restrict__ kc,
    const float* __restrict__ kr,
    const float* __restrict__ v,
    float* __restrict__ o)
{
    extern __shared__ float sm[];
    float* Qs = sm;
    float* Ks = Qs + 64*128;
    float* Vs = Ks + 64*128;
    float* Ps = Vs + 64*128;
    float* Ms = Ps + 64*64;
    float* Ls = Ms + 64;
    float* Cs = Ls + 64;

    const int qt  = blockIdx.x;
    const int h   = blockIdx.y;
    const int b   = blockIdx.z;
    const int tid = threadIdx.x;
    const int qbase = qt * 64;
    const size_t rowbase = (size_t)b * Tt;

    for (int i = tid; i < 64*32; i += 256) {
        int r  = i >> 5;
        int c4 = i & 31;
        *(float4*)(Qs + r*128 + c4*4) =
            *(const float4*)(q + (rowbase + qbase + r) * (Hh*HDd) + h*HDd + c4*4);
    }
    if (tid < 64) { Ms[tid] = -INFINITY; Ls[tid] = 0.f; }

    float acc[32];
    #pragma unroll
    for (int j = 0; j < 32; j++) acc[j] = 0.f;

    const int r  = tid >> 2;
    const int c0 = (tid & 3) * 16;
    const int d0 = (tid & 3) * 32;
    const float scale = 0.08838834764831845f;

    __syncthreads();

    for (int kb = 0; kb <= qt; kb++) {
        const int kbase = kb * 64;

        for (int i = tid; i < 64*32; i += 256) {
            int rr = i >> 5;
            int c4 = i & 31;
            size_t trow = rowbase + kbase + rr;
            float4 kval;
            if (c4 < 16)
                kval = *(const float4*)(kc + trow * (Hh*CDd) + h*CDd + c4*4);
            else
                kval = *(const float4*)(kr + trow * RDd + (c4-16)*4);
            *(float4*)(Ks + rr*128 + c4*4) = kval;
            *(float4*)(Vs + rr*128 + c4*4) =
                *(const float4*)(v + trow * (Hh*HDd) + h*HDd + c4*4);
        }
        __syncthreads();

        float s[16];
        #pragma unroll
        for (int j = 0; j < 16; j++) s[j] = 0.f;
        #pragma unroll 4
        for (int d = 0; d < 128; d += 4) {
            float4 q4 = *(const float4*)(Qs + r*128 + d);
            #pragma unroll
            for (int j = 0; j < 16; j++) {
                float4 k4 = *(const float4*)(Ks + (c0+j)*128 + d);
                s[j] += q4.x*k4.x + q4.y*k4.y + q4.z*k4.z + q4.w*k4.w;
            }
        }
        const bool diag = (kb == qt);
        #pragma unroll
        for (int j = 0; j < 16; j++) {
            float val = s[j] * scale;
            if (diag && (c0 + j) > r) val = -INFINITY;
            Ps[r*64 + c0 + j] = val;
        }
        __syncthreads();

        if (tid < 64) {
            float* prow = Ps + tid*64;
            float m_old = Ms[tid];
            float mx = m_old;
            #pragma unroll
            for (int c = 0; c < 64; c++) mx = fmaxf(mx, prow[c]);
            float cf = __expf(m_old - mx);
            float sum = 0.f;
            #pragma unroll
            for (int c = 0; c < 64; c++) {
                float p = __expf(prow[c] - mx);
                prow[c] = p;
                sum += p;
            }
            Ls[tid] = Ls[tid] * cf + sum;
            Ms[tid] = mx;
            Cs[tid] = cf;
        }
        __syncthreads();

        const float cf = Cs[r];
        #pragma unroll
        for (int j = 0; j < 32; j++) acc[j] *= cf;
        for (int c = 0; c < 64; c++) {
            float p = Ps[r*64 + c];
            const float* vrow = Vs + c*128 + d0;
            #pragma unroll
            for (int j = 0; j < 32; j += 4) {
                float4 v4 = *(const float4*)(vrow + j);
                acc[j]   += p * v4.x;
                acc[j+1] += p * v4.y;
                acc[j+2] += p * v4.z;
                acc[j+3] += p * v4.w;
            }
        }
        __syncthreads();
    }

    const float inv_l = 1.f / Ls[r];
    float* orow = o + (rowbase + qbase + r) * (Hh*HDd) + h*HDd + d0;
    #pragma unroll
    for (int j = 0; j < 32; j += 4) {
        float4 v4 = make_float4(acc[j]*inv_l, acc[j+1]*inv_l,
                                acc[j+2]*inv_l, acc[j+3]*inv_l);
        *(float4*)(orow + j) = v4;
    }
}

// ---------------------------------------------------------------------------
// Launch
// ---------------------------------------------------------------------------
extern "C" void kernel_launch(void* const* d_in, const int* in_sizes, int n_in,
                              void* d_out, int out_size)
{
    const float* x   = (const float*)d_in[0];
    const float* Wq  = (const float*)d_in[1];
    const float* bq  = (const float*)d_in[2];
    const float* Wkv = (const float*)d_in[3];
    const float* bkv = (const float*)d_in[4];
    const float* Wkr = (const float*)d_in[5];
    const float* bkr = (const float*)d_in[6];
    const float* Wku = (const float*)d_in[7];
    const float* bku = (const float*)d_in[8];
    const float* Wvu = (const float*)d_in[9];
    const float* bvu = (const float*)d_in[10];
    const float* Wo  = (const float*)d_in[11];
    const float* bo  = (const float*)d_in[12];
    float* out = (float*)d_out;

    float *qb, *kvb, *krb, *kcb, *vb, *ob;
    cudaGetSymbolAddress((void**)&qb,  g_q);
    cudaGetSymbolAddress((void**)&kvb, g_kv);
    cudaGetSymbolAddress((void**)&krb, g_kr);
    cudaGetSymbolAddress((void**)&kcb, g_kc);
    cudaGetSymbolAddress((void**)&vb,  g_v);
    cudaGetSymbolAddress((void**)&ob,  g_ao);

    cudaFuncSetAttribute(attn_kernel,
                         cudaFuncAttributeMaxDynamicSharedMemorySize,
                         ATT_SMEM_BYTES);

    const dim3 blk(256);

    // Projections from x (tf32 tensor-core GEMMs)
    gemm_tf32<<<dim3(16, 32), blk>>>(x, Dd, Wq,  bq,  qb,  Hh*HDd, Mrows, Hh*HDd, Dd);
    gemm_tf32<<<dim3(8,  32), blk>>>(x, Dd, Wkv, bkv, kvb, 2*LATd, Mrows, 2*LATd, Dd);
    gemm_tf32<<<dim3(1,  32), blk>>>(x, Dd, Wkr, bkr, krb, RDd,    Mrows, RDd,    Dd);

    rope_kr_kernel<<<Mrows, 32>>>(krb);

    gemm_tf32<<<dim3(8,  32), blk>>>(kvb,        2*LATd, Wku, bku, kcb, Hh*CDd, Mrows, Hh*CDd, LATd);
    gemm_tf32<<<dim3(16, 32), blk>>>(kvb + LATd, 2*LATd, Wvu, bvu, vb,  Hh*HDd, Mrows, Hh*HDd, LATd);

    rope_q_kernel<<<dim3(Mrows, Hh), 32>>>(qb);

    attn_kernel<<<dim3(Tt/64, Hh, Bb), blk, ATT_SMEM_BYTES>>>(qb, kcb, krb, vb, ob);

    gemm_tf32<<<dim3(16, 32), blk>>>(ob, Hh*HDd, Wo, bo, out, Dd, Mrows, Dd, Dd);
}

// round 4
// speedup vs baseline: 6.0971x; 5.3537x over previous
#include <cuda_runtime.h>
#include <cuda_bf16.h>
#include <math.h>
#include <stdint.h>

// Problem constants
#define Bb   2
#define Tt   2048
#define Dd   2048
#define Hh   16
#define HDd  128
#define LATd 512
#define RDd  64
#define CDd  64
#define Mrows (Bb*Tt)   // 4096

// ---------------------------------------------------------------------------
// Scratch (static device globals; no allocation allowed)
// ---------------------------------------------------------------------------
__device__ float g_q [Mrows * (Hh*HDd)];   // (4096, 2048)
__device__ float g_kv[Mrows * (2*LATd)];   // (4096, 1024)
__device__ float g_kr[Mrows * RDd];        // (4096, 64)
__device__ float g_kc[Mrows * (Hh*CDd)];   // (4096, 1024)
__device__ float g_v [Mrows * (Hh*HDd)];   // (4096, 2048)
__device__ float g_ao[Mrows * (Hh*HDd)];   // (4096, 2048)

// ---------------------------------------------------------------------------
// Common tf32 helpers (fragment layouts validated on HW in round 3)
// ---------------------------------------------------------------------------
__device__ __forceinline__ uint32_t f2tf32(float f) {
    uint32_t r;
    asm("cvt.rna.tf32.f32 %0, %1;" : "=r"(r) : "f"(f));
    return r;
}

__device__ __forceinline__ void mma_tf32(
    float& c0, float& c1, float& c2, float& c3,
    uint32_t a0, uint32_t a1, uint32_t a2, uint32_t a3,
    uint32_t b0, uint32_t b1)
{
    asm volatile(
        "mma.sync.aligned.m16n8k8.row.col.f32.tf32.tf32.f32 "
        "{%0,%1,%2,%3}, {%4,%5,%6,%7}, {%8,%9}, {%0,%1,%2,%3};\n"
        : "+f"(c0), "+f"(c1), "+f"(c2), "+f"(c3)
        : "r"(a0), "r"(a1), "r"(a2), "r"(a3), "r"(b0), "r"(b1));
}

// ---------------------------------------------------------------------------
// TF32 tensor-core GEMM: C(M,N) = A(M,K) @ W(N,K)^T + bias(N)   (unchanged)
// ---------------------------------------------------------------------------
#define BM 128
#define BN 128
#define BK 32
#define LDS_PAD 4
#define LDAs (BK + LDS_PAD)

__global__ void __launch_bounds__(256) gemm_tf32(
    const float* __restrict__ A, int lda,
    const float* __restrict__ W,
    const float* __restrict__ bias,
    float* __restrict__ C, int ldc,
    int M, int N, int K)
{
    __shared__ uint32_t As[BM][LDAs];
    __shared__ uint32_t Bs[BN][LDAs];

    const int tid  = threadIdx.x;
    const int warp = tid >> 5;
    const int lane = tid & 31;
    const int g    = lane >> 2;
    const int tg   = lane & 3;
    const int wm   = warp & 1;
    const int wn   = warp >> 1;
    const int bm   = blockIdx.y * BM;
    const int bn   = blockIdx.x * BN;
    const int wr0  = wm * 64;
    const int wn0  = wn * 32;

    float acc[4][4][4];
    #pragma unroll
    for (int mi = 0; mi < 4; mi++)
        #pragma unroll
        for (int ni = 0; ni < 4; ni++)
            #pragma unroll
            for (int r = 0; r < 4; r++) acc[mi][ni][r] = 0.f;

    for (int k0 = 0; k0 < K; k0 += BK) {
        #pragma unroll
        for (int it = 0; it < 4; it++) {
            int idx = tid + it * 256;
            int row = idx >> 3;
            int k4  = (idx & 7) * 4;
            float4 av = *(const float4*)(A + (size_t)(bm + row) * lda + k0 + k4);
            As[row][k4+0] = f2tf32(av.x);
            As[row][k4+1] = f2tf32(av.y);
            As[row][k4+2] = f2tf32(av.z);
            As[row][k4+3] = f2tf32(av.w);
            int nrow = bn + row;
            float4 bv = (nrow < N) ? *(const float4*)(W + (size_t)nrow * K + k0 + k4)
                                   : make_float4(0.f, 0.f, 0.f, 0.f);
            Bs[row][k4+0] = f2tf32(bv.x);
            Bs[row][k4+1] = f2tf32(bv.y);
            Bs[row][k4+2] = f2tf32(bv.z);
            Bs[row][k4+3] = f2tf32(bv.w);
        }
        __syncthreads();

        #pragma unroll
        for (int kk = 0; kk < BK; kk += 8) {
            uint32_t af[4][4], bf[4][2];
            #pragma unroll
            for (int mi = 0; mi < 4; mi++) {
                int r0 = wr0 + mi * 16 + g;
                af[mi][0] = As[r0    ][kk + tg];
                af[mi][1] = As[r0 + 8][kk + tg];
                af[mi][2] = As[r0    ][kk + tg + 4];
                af[mi][3] = As[r0 + 8][kk + tg + 4];
            }
            #pragma unroll
            for (int ni = 0; ni < 4; ni++) {
                int n0 = wn0 + ni * 8 + g;
                bf[ni][0] = Bs[n0][kk + tg];
                bf[ni][1] = Bs[n0][kk + tg + 4];
            }
            #pragma unroll
            for (int mi = 0; mi < 4; mi++)
                #pragma unroll
                for (int ni = 0; ni < 4; ni++)
                    mma_tf32(acc[mi][ni][0], acc[mi][ni][1],
                             acc[mi][ni][2], acc[mi][ni][3],
                             af[mi][0], af[mi][1], af[mi][2], af[mi][3],
                             bf[ni][0], bf[ni][1]);
        }
        __syncthreads();
    }

    #pragma unroll
    for (int mi = 0; mi < 4; mi++) {
        int row0 = bm + wr0 + mi * 16 + g;
        #pragma unroll
        for (int ni = 0; ni < 4; ni++) {
            int col = bn + wn0 + ni * 8 + 2 * tg;
            if (col < N) {
                float b0 = bias[col];
                float b1 = bias[col + 1];
                float* p0 = C + (size_t)row0 * ldc + col;
                float* p1 = C + (size_t)(row0 + 8) * ldc + col;
                p0[0] = acc[mi][ni][0] + b0;
                p0[1] = acc[mi][ni][1] + b1;
                p1[0] = acc[mi][ni][2] + b0;
                p1[1] = acc[mi][ni][3] + b1;
            }
        }
    }
}

// ---------------------------------------------------------------------------
// RoPE (rotate-half). RD=64, half=32.
// ---------------------------------------------------------------------------
__device__ __forceinline__ void rope_pair(float* p, int i, int t)
{
    float inv_freq = powf(10000.f, -(float)i / 32.f);
    float ang = (float)t * inv_freq;
    float s, c;
    sincosf(ang, &s, &c);
    float x1 = p[i];
    float x2 = p[i + 32];
    p[i]      = x1 * c - x2 * s;
    p[i + 32] = x2 * c + x1 * s;
}

__global__ void rope_kr_kernel(float* __restrict__ kr)
{
    int row = blockIdx.x;
    int t   = row & (Tt - 1);
    rope_pair(kr + (size_t)row * RDd, threadIdx.x, t);
}

__global__ void rope_q_kernel(float* __restrict__ qb)
{
    int row = blockIdx.x;
    int h   = blockIdx.y;
    int t   = row & (Tt - 1);
    rope_pair(qb + (size_t)row * (Hh*HDd) + h*HDd + CDd, threadIdx.x, t);
}

// ---------------------------------------------------------------------------
// Tensor-core flash attention (tf32 mma).
// Block: 64 q-rows x (head, batch). 4 warps, each owns 16 rows end-to-end.
// K tile 64. Q in registers (A-frags); K,V in smem (tf32); P via smem.
// smem strides chosen for conflict-free fragment access:
//   Ks stride 132 (=4 mod 32), Vs stride 136 (=8 mod 32), Ps stride 68.
// ---------------------------------------------------------------------------
#define AT_SQ 132
#define AT_SV 136
#define AT_SP 68
#define AT_SMEM_BYTES ((64*AT_SQ + 64*AT_SV + 64*AT_SP) * 4)

__global__ void __launch_bounds__(128, 2) attn_mma_kernel(
    const float* __restrict__ q,   // (4096, 2048)
    const float* __restrict__ kc,  // (4096, 1024)
    const float* __restrict__ kr,  // (4096, 64)
    const float* __restrict__ v,   // (4096, 2048)
    float* __restrict__ o)         // (4096, 2048)
{
    extern __shared__ uint32_t smu[];
    uint32_t* Ks = smu;                    // 64 x AT_SQ
    uint32_t* Vs = Ks + 64*AT_SQ;          // 64 x AT_SV
    uint32_t* Ps = Vs + 64*AT_SV;          // 64 x AT_SP

    const int qt   = (Tt/64 - 1) - blockIdx.x;   // heavy tiles first
    const int h    = blockIdx.y;
    const int b    = blockIdx.z;
    const int tid  = threadIdx.x;
    const int warp = tid >> 5;
    const int lane = tid & 31;
    const int g    = lane >> 2;
    const int tg   = lane & 3;
    const int m0   = warp * 16;
    const int qbase = qt * 64;
    const size_t rowbase = (size_t)b * Tt;
    const float scale = 0.08838834764831845f;    // 1/sqrt(128)

    // ---- Q fragments in registers: rows m0+g / m0+g+8, all 16 k-steps ----
    uint32_t aq[16][4];
    {
        const float* qA = q + (rowbase + qbase + m0 + g) * (Hh*HDd) + h*HDd;
        const float* qB = qA + 8 * (Hh*HDd);
        #pragma unroll
        for (int ks = 0; ks < 16; ks++) {
            int k0 = ks * 8;
            aq[ks][0] = f2tf32(qA[k0 + tg]);
            aq[ks][1] = f2tf32(qB[k0 + tg]);
            aq[ks][2] = f2tf32(qA[k0 + tg + 4]);
            aq[ks][3] = f2tf32(qB[k0 + tg + 4]);
        }
    }

    float oacc[16][4];
    #pragma unroll
    for (int na = 0; na < 16; na++)
        #pragma unroll
        for (int r = 0; r < 4; r++) oacc[na][r] = 0.f;

    float mA = -INFINITY, mB = -INFINITY;
    float lA = 0.f, lB = 0.f;

    for (int kb = 0; kb <= qt; kb++) {
        const int kbase = kb * 64;

        // ---- load K (content|rope) and V tiles into smem as tf32 ----
        for (int i = tid; i < 64*32; i += 128) {
            int rr = i >> 5;
            int c4 = i & 31;
            size_t trow = rowbase + kbase + rr;
            float4 kval;
            if (c4 < 16)
                kval = *(const float4*)(kc + trow * (Hh*CDd) + h*CDd + c4*4);
            else
                kval = *(const float4*)(kr + trow * RDd + (c4-16)*4);
            uint4 kt;
            kt.x = f2tf32(kval.x); kt.y = f2tf32(kval.y);
            kt.z = f2tf32(kval.z); kt.w = f2tf32(kval.w);
            *(uint4*)&Ks[rr*AT_SQ + c4*4] = kt;

            float4 vv = *(const float4*)(v + trow * (Hh*HDd) + h*HDd + c4*4);
            uint4 vt;
            vt.x = f2tf32(vv.x); vt.y = f2tf32(vv.y);
            vt.z = f2tf32(vv.z); vt.w = f2tf32(vv.w);
            *(uint4*)&Vs[rr*AT_SV + c4*4] = vt;
        }
        __syncthreads();

        // ---- S = Q @ K^T  (warp rows m0..m0+15, cols 0..63) ----
        float sacc[8][4];
        #pragma unroll
        for (int na = 0; na < 8; na++)
            #pragma unroll
            for (int r = 0; r < 4; r++) sacc[na][r] = 0.f;

        #pragma unroll
        for (int ks = 0; ks < 16; ks++) {
            #pragma unroll
            for (int na = 0; na < 8; na++) {
                uint32_t b0 = Ks[(na*8 + g)*AT_SQ + ks*8 + tg];
                uint32_t b1 = Ks[(na*8 + g)*AT_SQ + ks*8 + tg + 4];
                mma_tf32(sacc[na][0], sacc[na][1], sacc[na][2], sacc[na][3],
                         aq[ks][0], aq[ks][1], aq[ks][2], aq[ks][3], b0, b1);
            }
        }

        // ---- scale + causal mask + row max (registers only) ----
        const bool diag = (kb == qt);
        float mxA = -INFINITY, mxB = -INFINITY;
        #pragma unroll
        for (int na = 0; na < 8; na++) {
            float s0 = sacc[na][0] * scale;
            float s1 = sacc[na][1] * scale;
            float s2 = sacc[na][2] * scale;
            float s3 = sacc[na][3] * scale;
            if (diag) {
                int c  = na*8 + 2*tg;
                int rA = m0 + g;
                int rB = rA + 8;
                if (c     > rA) s0 = -INFINITY;
                if (c + 1 > rA) s1 = -INFINITY;
                if (c     > rB) s2 = -INFINITY;
                if (c + 1 > rB) s3 = -INFINITY;
            }
            sacc[na][0] = s0; sacc[na][1] = s1;
            sacc[na][2] = s2; sacc[na][3] = s3;
            mxA = fmaxf(mxA, fmaxf(s0, s1));
            mxB = fmaxf(mxB, fmaxf(s2, s3));
        }
        // reduce max over the 4 tg lanes sharing each row
        mxA = fmaxf(mxA, __shfl_xor_sync(0xffffffff, mxA, 1));
        mxA = fmaxf(mxA, __shfl_xor_sync(0xffffffff, mxA, 2));
        mxB = fmaxf(mxB, __shfl_xor_sync(0xffffffff, mxB, 1));
        mxB = fmaxf(mxB, __shfl_xor_sync(0xffffffff, mxB, 2));

        float mnA = fmaxf(mA, mxA);
        float mnB = fmaxf(mB, mxB);
        float cfA = __expf(mA - mnA);    // 0 when mA == -inf
        float cfB = __expf(mB - mnB);
        mA = mnA; mB = mnB;

        // ---- p = exp(s - m); write P to smem in tf32; partial row sums ----
        float sumA = 0.f, sumB = 0.f;
        uint32_t* prowA = Ps + (m0 + g) * AT_SP;
        uint32_t* prowB = prowA + 8 * AT_SP;
        #pragma unroll
        for (int na = 0; na < 8; na++) {
            int c = na*8 + 2*tg;
            float p0 = __expf(sacc[na][0] - mA);
            float p1 = __expf(sacc[na][1] - mA);
            float p2 = __expf(sacc[na][2] - mB);
            float p3 = __expf(sacc[na][3] - mB);
            sumA += p0 + p1;
            sumB += p2 + p3;
            prowA[c]     = f2tf32(p0);
            prowA[c + 1] = f2tf32(p1);
            prowB[c]     = f2tf32(p2);
            prowB[c + 1] = f2tf32(p3);
        }
        lA = lA * cfA + sumA;            // per-thread partial; reduced at end
        lB = lB * cfB + sumB;

        // rescale O accumulator
        #pragma unroll
        for (int na = 0; na < 16; na++) {
            oacc[na][0] *= cfA; oacc[na][1] *= cfA;
            oacc[na][2] *= cfB; oacc[na][3] *= cfB;
        }

        __syncwarp();   // P rows are warp-private; order STS before LDS

        // ---- O += P @ V ----
        #pragma unroll
        for (int ks = 0; ks < 8; ks++) {
            uint32_t pa0 = Ps[(m0 + g)     * AT_SP + ks*8 + tg];
            uint32_t pa1 = Ps[(m0 + g + 8) * AT_SP + ks*8 + tg];
            uint32_t pa2 = Ps[(m0 + g)     * AT_SP + ks*8 + tg + 4];
            uint32_t pa3 = Ps[(m0 + g + 8) * AT_SP + ks*8 + tg + 4];
            #pragma unroll
            for (int na = 0; na < 16; na++) {
                uint32_t b0 = Vs[(ks*8 + tg)     * AT_SV + na*8 + g];
                uint32_t b1 = Vs[(ks*8 + tg + 4) * AT_SV + na*8 + g];
                mma_tf32(oacc[na][0], oacc[na][1], oacc[na][2], oacc[na][3],
                         pa0, pa1, pa2, pa3, b0, b1);
            }
        }
        __syncthreads();   // before next tile overwrites Ks/Vs
    }

    // ---- final: reduce l over tg lanes, normalize, store ----
    lA += __shfl_xor_sync(0xffffffff, lA, 1);
    lA += __shfl_xor_sync(0xffffffff, lA, 2);
    lB += __shfl_xor_sync(0xffffffff, lB, 1);
    lB += __shfl_xor_sync(0xffffffff, lB, 2);
    float invA = 1.f / lA;
    float invB = 1.f / lB;

    float* oA = o + (rowbase + qbase + m0 + g) * (Hh*HDd) + h*HDd;
    float* oB = oA + 8 * (Hh*HDd);
    #pragma unroll
    for (int na = 0; na < 16; na++) {
        int c = na*8 + 2*tg;
        *(float2*)(oA + c) = make_float2(oacc[na][0]*invA, oacc[na][1]*invA);
        *(float2*)(oB + c) = make_float2(oacc[na][2]*invB, oacc[na][3]*invB);
    }
}

// ---------------------------------------------------------------------------
// Launch
// ---------------------------------------------------------------------------
extern "C" void kernel_launch(void* const* d_in, const int* in_sizes, int n_in,
                              void* d_out, int out_size)
{
    const float* x   = (const float*)d_in[0];
    const float* Wq  = (const float*)d_in[1];
    const float* bq  = (const float*)d_in[2];
    const float* Wkv = (const float*)d_in[3];
    const float* bkv = (const float*)d_in[4];
    const float* Wkr = (const float*)d_in[5];
    const float* bkr = (const float*)d_in[6];
    const float* Wku = (const float*)d_in[7];
    const float* bku = (const float*)d_in[8];
    const float* Wvu = (const float*)d_in[9];
    const float* bvu = (const float*)d_in[10];
    const float* Wo  = (const float*)d_in[11];
    const float* bo  = (const float*)d_in[12];
    float* out = (float*)d_out;

    float *qb, *kvb, *krb, *kcb, *vb, *ob;
    cudaGetSymbolAddress((void**)&qb,  g_q);
    cudaGetSymbolAddress((void**)&kvb, g_kv);
    cudaGetSymbolAddress((void**)&krb, g_kr);
    cudaGetSymbolAddress((void**)&kcb, g_kc);
    cudaGetSymbolAddress((void**)&vb,  g_v);
    cudaGetSymbolAddress((void**)&ob,  g_ao);

    cudaFuncSetAttribute(attn_mma_kernel,
                         cudaFuncAttributeMaxDynamicSharedMemorySize,
                         AT_SMEM_BYTES);

    const dim3 blk(256);

    // Projections from x (tf32 tensor-core GEMMs)
    gemm_tf32<<<dim3(16, 32), blk>>>(x, Dd, Wq,  bq,  qb,  Hh*HDd, Mrows, Hh*HDd, Dd);
    gemm_tf32<<<dim3(8,  32), blk>>>(x, Dd, Wkv, bkv, kvb, 2*LATd, Mrows, 2*LATd, Dd);
    gemm_tf32<<<dim3(1,  32), blk>>>(x, Dd, Wkr, bkr, krb, RDd,    Mrows, RDd,    Dd);

    rope_kr_kernel<<<Mrows, 32>>>(krb);

    gemm_tf32<<<dim3(8,  32), blk>>>(kvb,        2*LATd, Wku, bku, kcb, Hh*CDd, Mrows, Hh*CDd, LATd);
    gemm_tf32<<<dim3(16, 32), blk>>>(kvb + LATd, 2*LATd, Wvu, bvu, vb,  Hh*HDd, Mrows, Hh*HDd, LATd);

    rope_q_kernel<<<dim3(Mrows, Hh), 32>>>(qb);

    attn_mma_kernel<<<dim3(Tt/64, Hh, Bb), dim3(128), AT_SMEM_BYTES>>>(qb, kcb, krb, vb, ob);

    gemm_tf32<<<dim3(16, 32), blk>>>(ob, Hh*HDd, Wo, bo, out, Dd, Mrows, Dd, Dd);
}

// round 5
// speedup vs baseline: 8.7812x; 1.4402x over previous
#include <cuda_runtime.h>
#include <cuda_bf16.h>
#include <math.h>
#include <stdint.h>

// Problem constants
#define Bb   2
#define Tt   2048
#define Dd   2048
#define Hh   16
#define HDd  128
#define LATd 512
#define RDd  64
#define CDd  64
#define Mrows (Bb*Tt)   // 4096

// ---------------------------------------------------------------------------
// Scratch (static device globals; no allocation allowed)
// ---------------------------------------------------------------------------
__device__ float g_q [Mrows * (Hh*HDd)];
__device__ float g_kv[Mrows * (2*LATd)];
__device__ float g_kr[Mrows * RDd];
__device__ float g_kc[Mrows * (Hh*CDd)];
__device__ float g_v [Mrows * (Hh*HDd)];
__device__ float g_ao[Mrows * (Hh*HDd)];

// ---------------------------------------------------------------------------
// Common tf32 helpers (fragment layouts HW-validated in rounds 3/4)
// ---------------------------------------------------------------------------
__device__ __forceinline__ uint32_t f2tf32(float f) {
    uint32_t r;
    asm("cvt.rna.tf32.f32 %0, %1;" : "=r"(r) : "f"(f));
    return r;
}

__device__ __forceinline__ void mma_tf32(
    float& c0, float& c1, float& c2, float& c3,
    uint32_t a0, uint32_t a1, uint32_t a2, uint32_t a3,
    uint32_t b0, uint32_t b1)
{
    asm volatile(
        "mma.sync.aligned.m16n8k8.row.col.f32.tf32.tf32.f32 "
        "{%0,%1,%2,%3}, {%4,%5,%6,%7}, {%8,%9}, {%0,%1,%2,%3};\n"
        : "+f"(c0), "+f"(c1), "+f"(c2), "+f"(c3)
        : "r"(a0), "r"(a1), "r"(a2), "r"(a3), "r"(b0), "r"(b1));
}

__device__ __forceinline__ void cp_async16(uint32_t dst_smem, const void* src, int src_bytes) {
    asm volatile("cp.async.cg.shared.global [%0], [%1], 16, %2;\n"
                 :: "r"(dst_smem), "l"(src), "r"(src_bytes));
}
#define CP_COMMIT() asm volatile("cp.async.commit_group;\n" ::: "memory")
#define CP_WAIT1()  asm volatile("cp.async.wait_group 1;\n" ::: "memory")

// ---------------------------------------------------------------------------
// TF32 GEMM, cp.async double-buffered: C(M,N) = A(M,K) @ W(N,K)^T + bias(N)
// 128x128x32 tiles, 256 threads, warp tile 64x32 (4x4 m16n8k8).
// smem holds raw fp32 (2 stages); tf32 conversion on fragment load.
// M%128==0, K%32==0. N guarded (zero-filled cp.async + epilogue guard).
// ---------------------------------------------------------------------------
#define BM 128
#define BN 128
#define BK 32
#define GST 36                       // smem row stride (floats), %32==4
#define G_ASZ (BM*GST)               // floats per A stage
#define GEMM_SMEM_BYTES (4 * G_ASZ * 4)   // 2 stages * (A+B) = 73728 B

__global__ void __launch_bounds__(256) gemm_tf32(
    const float* __restrict__ A, int lda,
    const float* __restrict__ W,
    const float* __restrict__ bias,
    float* __restrict__ C, int ldc,
    int M, int N, int K)
{
    extern __shared__ float smemf[];
    // layout: As stage0 | As stage1 | Bs stage0 | Bs stage1
    const uint32_t smem_u32 = (uint32_t)__cvta_generic_to_shared(smemf);

    const int tid  = threadIdx.x;
    const int warp = tid >> 5;
    const int lane = tid & 31;
    const int g    = lane >> 2;
    const int tg   = lane & 3;
    const int wm   = warp & 1;
    const int wn   = warp >> 1;
    const int bm   = blockIdx.y * BM;
    const int bn   = blockIdx.x * BN;
    const int wr0  = wm * 64;
    const int wn0  = wn * 32;

    // this thread's 4 load slots (row, k4) for each of A and B
    const int lrow0 = tid >> 3;          // slots tid + it*256 -> rows
    const int lk4   = (tid & 7) * 4;

    float acc[4][4][4];
    #pragma unroll
    for (int mi = 0; mi < 4; mi++)
        #pragma unroll
        for (int ni = 0; ni < 4; ni++)
            #pragma unroll
            for (int r = 0; r < 4; r++) acc[mi][ni][r] = 0.f;

    const int ntiles = K / BK;

    // prefetch helper (macro-free, inlined by unroll)
    auto prefetch = [&](int k0, int stage) {
        #pragma unroll
        for (int it = 0; it < 4; it++) {
            int row = lrow0 + it * 32;
            uint32_t adst = smem_u32 + (uint32_t)((stage*G_ASZ + row*GST + lk4) * 4);
            cp_async16(adst, A + (size_t)(bm + row) * lda + k0 + lk4, 16);
            int nrow = bn + row;
            uint32_t bdst = smem_u32 + (uint32_t)(((2 + stage)*G_ASZ + row*GST + lk4) * 4);
            cp_async16(bdst, W + (size_t)(nrow < N ? nrow : 0) * K + k0 + lk4,
                       nrow < N ? 16 : 0);
        }
    };

    prefetch(0, 0);
    CP_COMMIT();

    for (int t = 0; t < ntiles; t++) {
        if (t + 1 < ntiles) prefetch((t + 1) * BK, (t + 1) & 1);
        CP_COMMIT();
        CP_WAIT1();
        __syncthreads();

        const float* Asb = smemf + (t & 1) * G_ASZ;
        const float* Bsb = smemf + (2 + (t & 1)) * G_ASZ;

        #pragma unroll
        for (int kk = 0; kk < BK; kk += 8) {
            uint32_t af[4][4], bf[4][2];
            #pragma unroll
            for (int mi = 0; mi < 4; mi++) {
                int r0 = wr0 + mi * 16 + g;
                af[mi][0] = f2tf32(Asb[r0*GST       + kk + tg]);
                af[mi][1] = f2tf32(Asb[(r0+8)*GST   + kk + tg]);
                af[mi][2] = f2tf32(Asb[r0*GST       + kk + tg + 4]);
                af[mi][3] = f2tf32(Asb[(r0+8)*GST   + kk + tg + 4]);
            }
            #pragma unroll
            for (int ni = 0; ni < 4; ni++) {
                int n0 = wn0 + ni * 8 + g;
                bf[ni][0] = f2tf32(Bsb[n0*GST + kk + tg]);
                bf[ni][1] = f2tf32(Bsb[n0*GST + kk + tg + 4]);
            }
            #pragma unroll
            for (int mi = 0; mi < 4; mi++)
                #pragma unroll
                for (int ni = 0; ni < 4; ni++)
                    mma_tf32(acc[mi][ni][0], acc[mi][ni][1],
                             acc[mi][ni][2], acc[mi][ni][3],
                             af[mi][0], af[mi][1], af[mi][2], af[mi][3],
                             bf[ni][0], bf[ni][1]);
        }
        __syncthreads();
    }

    #pragma unroll
    for (int mi = 0; mi < 4; mi++) {
        int row0 = bm + wr0 + mi * 16 + g;
        #pragma unroll
        for (int ni = 0; ni < 4; ni++) {
            int col = bn + wn0 + ni * 8 + 2 * tg;
            if (col < N) {
                float b0 = bias[col];
                float b1 = bias[col + 1];
                float* p0 = C + (size_t)row0 * ldc + col;
                float* p1 = C + (size_t)(row0 + 8) * ldc + col;
                p0[0] = acc[mi][ni][0] + b0;
                p0[1] = acc[mi][ni][1] + b1;
                p1[0] = acc[mi][ni][2] + b0;
                p1[1] = acc[mi][ni][3] + b1;
            }
        }
    }
}

// ---------------------------------------------------------------------------
// RoPE (rotate-half). RD=64, half=32.
// ---------------------------------------------------------------------------
__device__ __forceinline__ void rope_pair(float* p, int i, int t)
{
    float inv_freq = powf(10000.f, -(float)i / 32.f);
    float ang = (float)t * inv_freq;
    float s, c;
    sincosf(ang, &s, &c);
    float x1 = p[i];
    float x2 = p[i + 32];
    p[i]      = x1 * c - x2 * s;
    p[i + 32] = x2 * c + x1 * s;
}

__global__ void rope_kr_kernel(float* __restrict__ kr)
{
    int row = blockIdx.x;
    int t   = row & (Tt - 1);
    rope_pair(kr + (size_t)row * RDd, threadIdx.x, t);
}

__global__ void rope_q_kernel(float* __restrict__ qb)
{
    int row = blockIdx.x;
    int h   = blockIdx.y;
    int t   = row & (Tt - 1);
    rope_pair(qb + (size_t)row * (Hh*HDd) + h*HDd + CDd, threadIdx.x, t);
}

// ---------------------------------------------------------------------------
// Tensor-core flash attention (tf32 mma) — unchanged from round 4.
// ---------------------------------------------------------------------------
#define AT_SQ 132
#define AT_SV 136
#define AT_SP 68
#define AT_SMEM_BYTES ((64*AT_SQ + 64*AT_SV + 64*AT_SP) * 4)

__global__ void __launch_bounds__(128, 2) attn_mma_kernel(
    const float* __restrict__ q,
    const float* __restrict__ kc,
    const float* __restrict__ kr,
    const float* __restrict__ v,
    float* __restrict__ o)
{
    extern __shared__ uint32_t smu[];
    uint32_t* Ks = smu;
    uint32_t* Vs = Ks + 64*AT_SQ;
    uint32_t* Ps = Vs + 64*AT_SV;

    const int qt   = (Tt/64 - 1) - blockIdx.x;
    const int h    = blockIdx.y;
    const int b    = blockIdx.z;
    const int tid  = threadIdx.x;
    const int warp = tid >> 5;
    const int lane = tid & 31;
    const int g    = lane >> 2;
    const int tg   = lane & 3;
    const int m0   = warp * 16;
    const int qbase = qt * 64;
    const size_t rowbase = (size_t)b * Tt;
    const float scale = 0.08838834764831845f;

    uint32_t aq[16][4];
    {
        const float* qA = q + (rowbase + qbase + m0 + g) * (Hh*HDd) + h*HDd;
        const float* qB = qA + 8 * (Hh*HDd);
        #pragma unroll
        for (int ks = 0; ks < 16; ks++) {
            int k0 = ks * 8;
            aq[ks][0] = f2tf32(qA[k0 + tg]);
            aq[ks][1] = f2tf32(qB[k0 + tg]);
            aq[ks][2] = f2tf32(qA[k0 + tg + 4]);
            aq[ks][3] = f2tf32(qB[k0 + tg + 4]);
        }
    }

    float oacc[16][4];
    #pragma unroll
    for (int na = 0; na < 16; na++)
        #pragma unroll
        for (int r = 0; r < 4; r++) oacc[na][r] = 0.f;

    float mA = -INFINITY, mB = -INFINITY;
    float lA = 0.f, lB = 0.f;

    for (int kb = 0; kb <= qt; kb++) {
        const int kbase = kb * 64;

        for (int i = tid; i < 64*32; i += 128) {
            int rr = i >> 5;
            int c4 = i & 31;
            size_t trow = rowbase + kbase + rr;
            float4 kval;
            if (c4 < 16)
                kval = *(const float4*)(kc + trow * (Hh*CDd) + h*CDd + c4*4);
            else
                kval = *(const float4*)(kr + trow * RDd + (c4-16)*4);
            uint4 kt;
            kt.x = f2tf32(kval.x); kt.y = f2tf32(kval.y);
            kt.z = f2tf32(kval.z); kt.w = f2tf32(kval.w);
            *(uint4*)&Ks[rr*AT_SQ + c4*4] = kt;

            float4 vv = *(const float4*)(v + trow * (Hh*HDd) + h*HDd + c4*4);
            uint4 vt;
            vt.x = f2tf32(vv.x); vt.y = f2tf32(vv.y);
            vt.z = f2tf32(vv.z); vt.w = f2tf32(vv.w);
            *(uint4*)&Vs[rr*AT_SV + c4*4] = vt;
        }
        __syncthreads();

        float sacc[8][4];
        #pragma unroll
        for (int na = 0; na < 8; na++)
            #pragma unroll
            for (int r = 0; r < 4; r++) sacc[na][r] = 0.f;

        #pragma unroll
        for (int ks = 0; ks < 16; ks++) {
            #pragma unroll
            for (int na = 0; na < 8; na++) {
                uint32_t b0 = Ks[(na*8 + g)*AT_SQ + ks*8 + tg];
                uint32_t b1 = Ks[(na*8 + g)*AT_SQ + ks*8 + tg + 4];
                mma_tf32(sacc[na][0], sacc[na][1], sacc[na][2], sacc[na][3],
                         aq[ks][0], aq[ks][1], aq[ks][2], aq[ks][3], b0, b1);
            }
        }

        const bool diag = (kb == qt);
        float mxA = -INFINITY, mxB = -INFINITY;
        #pragma unroll
        for (int na = 0; na < 8; na++) {
            float s0 = sacc[na][0] * scale;
            float s1 = sacc[na][1] * scale;
            float s2 = sacc[na][2] * scale;
            float s3 = sacc[na][3] * scale;
            if (diag) {
                int c  = na*8 + 2*tg;
                int rA = m0 + g;
                int rB = rA + 8;
                if (c     > rA) s0 = -INFINITY;
                if (c + 1 > rA) s1 = -INFINITY;
                if (c     > rB) s2 = -INFINITY;
                if (c + 1 > rB) s3 = -INFINITY;
            }
            sacc[na][0] = s0; sacc[na][1] = s1;
            sacc[na][2] = s2; sacc[na][3] = s3;
            mxA = fmaxf(mxA, fmaxf(s0, s1));
            mxB = fmaxf(mxB, fmaxf(s2, s3));
        }
        mxA = fmaxf(mxA, __shfl_xor_sync(0xffffffff, mxA, 1));
        mxA = fmaxf(mxA, __shfl_xor_sync(0xffffffff, mxA, 2));
        mxB = fmaxf(mxB, __shfl_xor_sync(0xffffffff, mxB, 1));
        mxB = fmaxf(mxB, __shfl_xor_sync(0xffffffff, mxB, 2));

        float mnA = fmaxf(mA, mxA);
        float mnB = fmaxf(mB, mxB);
        float cfA = __expf(mA - mnA);
        float cfB = __expf(mB - mnB);
        mA = mnA; mB = mnB;

        float sumA = 0.f, sumB = 0.f;
        uint32_t* prowA = Ps + (m0 + g) * AT_SP;
        uint32_t* prowB = prowA + 8 * AT_SP;
        #pragma unroll
        for (int na = 0; na < 8; na++) {
            int c = na*8 + 2*tg;
            float p0 = __expf(sacc[na][0] - mA);
            float p1 = __expf(sacc[na][1] - mA);
            float p2 = __expf(sacc[na][2] - mB);
            float p3 = __expf(sacc[na][3] - mB);
            sumA += p0 + p1;
            sumB += p2 + p3;
            prowA[c]     = f2tf32(p0);
            prowA[c + 1] = f2tf32(p1);
            prowB[c]     = f2tf32(p2);
            prowB[c + 1] = f2tf32(p3);
        }
        lA = lA * cfA + sumA;
        lB = lB * cfB + sumB;

        #pragma unroll
        for (int na = 0; na < 16; na++) {
            oacc[na][0] *= cfA; oacc[na][1] *= cfA;
            oacc[na][2] *= cfB; oacc[na][3] *= cfB;
        }

        __syncwarp();

        #pragma unroll
        for (int ks = 0; ks < 8; ks++) {
            uint32_t pa0 = Ps[(m0 + g)     * AT_SP + ks*8 + tg];
            uint32_t pa1 = Ps[(m0 + g + 8) * AT_SP + ks*8 + tg];
            uint32_t pa2 = Ps[(m0 + g)     * AT_SP + ks*8 + tg + 4];
            uint32_t pa3 = Ps[(m0 + g + 8) * AT_SP + ks*8 + tg + 4];
            #pragma unroll
            for (int na = 0; na < 16; na++) {
                uint32_t b0 = Vs[(ks*8 + tg)     * AT_SV + na*8 + g];
                uint32_t b1 = Vs[(ks*8 + tg + 4) * AT_SV + na*8 + g];
                mma_tf32(oacc[na][0], oacc[na][1], oacc[na][2], oacc[na][3],
                         pa0, pa1, pa2, pa3, b0, b1);
            }
        }
        __syncthreads();
    }

    lA += __shfl_xor_sync(0xffffffff, lA, 1);
    lA += __shfl_xor_sync(0xffffffff, lA, 2);
    lB += __shfl_xor_sync(0xffffffff, lB, 1);
    lB += __shfl_xor_sync(0xffffffff, lB, 2);
    float invA = 1.f / lA;
    float invB = 1.f / lB;

    float* oA = o + (rowbase + qbase + m0 + g) * (Hh*HDd) + h*HDd;
    float* oB = oA + 8 * (Hh*HDd);
    #pragma unroll
    for (int na = 0; na < 16; na++) {
        int c = na*8 + 2*tg;
        *(float2*)(oA + c) = make_float2(oacc[na][0]*invA, oacc[na][1]*invA);
        *(float2*)(oB + c) = make_float2(oacc[na][2]*invB, oacc[na][3]*invB);
    }
}

// ---------------------------------------------------------------------------
// Launch
// ---------------------------------------------------------------------------
extern "C" void kernel_launch(void* const* d_in, const int* in_sizes, int n_in,
                              void* d_out, int out_size)
{
    const float* x   = (const float*)d_in[0];
    const float* Wq  = (const float*)d_in[1];
    const float* bq  = (const float*)d_in[2];
    const float* Wkv = (const float*)d_in[3];
    const float* bkv = (const float*)d_in[4];
    const float* Wkr = (const float*)d_in[5];
    const float* bkr = (const float*)d_in[6];
    const float* Wku = (const float*)d_in[7];
    const float* bku = (const float*)d_in[8];
    const float* Wvu = (const float*)d_in[9];
    const float* bvu = (const float*)d_in[10];
    const float* Wo  = (const float*)d_in[11];
    const float* bo  = (const float*)d_in[12];
    float* out = (float*)d_out;

    float *qb, *kvb, *krb, *kcb, *vb, *ob;
    cudaGetSymbolAddress((void**)&qb,  g_q);
    cudaGetSymbolAddress((void**)&kvb, g_kv);
    cudaGetSymbolAddress((void**)&krb, g_kr);
    cudaGetSymbolAddress((void**)&kcb, g_kc);
    cudaGetSymbolAddress((void**)&vb,  g_v);
    cudaGetSymbolAddress((void**)&ob,  g_ao);

    cudaFuncSetAttribute(gemm_tf32,
                         cudaFuncAttributeMaxDynamicSharedMemorySize,
                         GEMM_SMEM_BYTES);
    cudaFuncSetAttribute(attn_mma_kernel,
                         cudaFuncAttributeMaxDynamicSharedMemorySize,
                         AT_SMEM_BYTES);

    const dim3 blk(256);

    gemm_tf32<<<dim3(16, 32), blk, GEMM_SMEM_BYTES>>>(x, Dd, Wq,  bq,  qb,  Hh*HDd, Mrows, Hh*HDd, Dd);
    gemm_tf32<<<dim3(8,  32), blk, GEMM_SMEM_BYTES>>>(x, Dd, Wkv, bkv, kvb, 2*LATd, Mrows, 2*LATd, Dd);
    gemm_tf32<<<dim3(1,  32), blk, GEMM_SMEM_BYTES>>>(x, Dd, Wkr, bkr, krb, RDd,    Mrows, RDd,    Dd);

    rope_kr_kernel<<<Mrows, 32>>>(krb);

    gemm_tf32<<<dim3(8,  32), blk, GEMM_SMEM_BYTES>>>(kvb,        2*LATd, Wku, bku, kcb, Hh*CDd, Mrows, Hh*CDd, LATd);
    gemm_tf32<<<dim3(16, 32), blk, GEMM_SMEM_BYTES>>>(kvb + LATd, 2*LATd, Wvu, bvu, vb,  Hh*HDd, Mrows, Hh*HDd, LATd);

    rope_q_kernel<<<dim3(Mrows, Hh), 32>>>(qb);

    attn_mma_kernel<<<dim3(Tt/64, Hh, Bb), dim3(128), AT_SMEM_BYTES>>>(qb, kcb, krb, vb, ob);

    gemm_tf32<<<dim3(16, 32), blk, GEMM_SMEM_BYTES>>>(ob, Hh*HDd, Wo, bo, out, Dd, Mrows, Dd, Dd);
}